// round 2
// baseline (speedup 1.0000x reference)
#include <cuda_runtime.h>

#define NUM_GRAPHS 16384
#define C 128
#define C2 256

// Scratch (static device globals — no allocation in kernel_launch)
__device__ int   g_offs[NUM_GRAPHS + 1];
__device__ float g_pooled[(size_t)NUM_GRAPHS * C];

// ---------------------------------------------------------------------------
// Kernel 0: segment offsets via binary search (batch sorted; dtype-robust).
// JAX with x64 disabled stores "int64" as int32 — detect layout on device:
// pick an odd 32-bit word index < N. int64 layout -> that word is a high
// word (== 0 since ids < 2^31). int32 layout -> it's a late batch id (> 0).
// ---------------------------------------------------------------------------
__global__ void seg_offsets_kernel(const int* __restrict__ batch32, int n) {
    int g = blockIdx.x * blockDim.x + threadIdx.x;
    if (g > NUM_GRAPHS) return;

    int probe_idx = ((n - 1) & 1) ? (n - 1) : (n - 2);   // odd index < n
    bool is_i32 = (probe_idx >= 1) && (batch32[probe_idx] != 0);

    int lo = 0, hi = n;
    if (is_i32) {
        while (lo < hi) {
            int mid = (lo + hi) >> 1;
            if (batch32[mid] < g) lo = mid + 1; else hi = mid;
        }
    } else {
        const long long* b64 = (const long long*)batch32;
        long long target = (long long)g;
        while (lo < hi) {
            int mid = (lo + hi) >> 1;
            if (b64[mid] < target) lo = mid + 1; else hi = mid;
        }
    }
    g_offs[g] = lo;
}

// ---------------------------------------------------------------------------
// Kernel 1: fused gate + online segment-softmax + weighted pooling.
// One warp per graph. Each lane owns 4 channels (float4). Single pass over x.
// ---------------------------------------------------------------------------
__global__ __launch_bounds__(256) void pool_kernel(
    const float4* __restrict__ x4,        // [N, 32] float4 view of [N,128]
    const float4* __restrict__ gate_w4,   // [32] float4 view of [128]
    const float*  __restrict__ gate_b)    // [1]
{
    const int warp = threadIdx.x >> 5;
    const int lane = threadIdx.x & 31;
    const int g = blockIdx.x * 8 + warp;

    const int lo = g_offs[g];
    const int hi = g_offs[g + 1];

    const float4 gw = gate_w4[lane];
    const float  gb = gate_b[0];

    float  m = -INFINITY;
    float  s = 0.0f;
    float4 acc = make_float4(0.f, 0.f, 0.f, 0.f);

    const float4* row = x4 + (size_t)lo * 32;
    float4 v = make_float4(0.f, 0.f, 0.f, 0.f);
    if (lo < hi) v = row[lane];

    for (int r = lo; r < hi; ++r) {
        // prefetch next row (software pipeline)
        float4 vn = make_float4(0.f, 0.f, 0.f, 0.f);
        if (r + 1 < hi) vn = row[32 + lane];
        row += 32;

        // gate score: dot(x_row, gate_w) via warp reduce
        float p = v.x * gw.x + v.y * gw.y + v.z * gw.z + v.w * gw.w;
        #pragma unroll
        for (int o = 16; o > 0; o >>= 1)
            p += __shfl_xor_sync(0xffffffffu, p, o);
        float gsc = p + gb;

        // online softmax update
        float m_new = fmaxf(m, gsc);
        float alpha = __expf(m - m_new);   // __expf(-inf) = 0 on first iter
        float e     = __expf(gsc - m_new);
        s = s * alpha + e;
        acc.x = fmaf(acc.x, alpha, e * v.x);
        acc.y = fmaf(acc.y, alpha, e * v.y);
        acc.z = fmaf(acc.z, alpha, e * v.z);
        acc.w = fmaf(acc.w, alpha, e * v.w);
        m = m_new;
        v = vn;
    }

    float inv = (hi > lo) ? __frcp_rn(s) : 0.0f;
    float4 out;
    out.x = acc.x * inv;
    out.y = acc.y * inv;
    out.z = acc.z * inv;
    out.w = acc.w * inv;
    reinterpret_cast<float4*>(g_pooled)[(size_t)g * 32 + lane] = out;
}

// ---------------------------------------------------------------------------
// Kernel 2: out = pooled @ nn_w + nn_b, with empty-graph zeroing.
// Block = 256 threads (one output column each), 16 graphs per block.
// ---------------------------------------------------------------------------
__global__ __launch_bounds__(256) void gemm_kernel(
    const float* __restrict__ nn_w,   // [128, 256] row-major
    const float* __restrict__ nn_b,   // [256]
    float* __restrict__ out)          // [16384, 256]
{
    __shared__ float ps[16][C];       // pooled tile: 16 graphs x 128 ch = 8 KB

    const int t  = threadIdx.x;       // 0..255 -> output column j
    const int g0 = blockIdx.x * 16;

    // cooperative load of pooled tile (float4, coalesced)
    {
        const float4* src = reinterpret_cast<const float4*>(g_pooled + (size_t)g0 * C);
        float4* dst = reinterpret_cast<float4*>(&ps[0][0]);
        dst[t]       = src[t];
        dst[t + 256] = src[t + 256];
    }
    __syncthreads();

    const int j = t;
    float accs[16];
    #pragma unroll
    for (int g = 0; g < 16; ++g) accs[g] = 0.0f;

    #pragma unroll 1
    for (int k = 0; k < C; k += 4) {
        // 4 rows of W, column j (coalesced across the warp; L1-resident)
        float w0 = nn_w[(k + 0) * C2 + j];
        float w1 = nn_w[(k + 1) * C2 + j];
        float w2 = nn_w[(k + 2) * C2 + j];
        float w3 = nn_w[(k + 3) * C2 + j];
        #pragma unroll
        for (int g = 0; g < 16; ++g) {
            float4 p = *reinterpret_cast<const float4*>(&ps[g][k]);  // LDS.128 broadcast
            float a = accs[g];
            a = fmaf(p.x, w0, a);
            a = fmaf(p.y, w1, a);
            a = fmaf(p.z, w2, a);
            a = fmaf(p.w, w3, a);
            accs[g] = a;
        }
    }

    const float b = nn_b[j];
    #pragma unroll
    for (int g = 0; g < 16; ++g) {
        bool nonempty = g_offs[g0 + g + 1] > g_offs[g0 + g];
        out[(size_t)(g0 + g) * C2 + j] = nonempty ? (accs[g] + b) : 0.0f;
    }
}

// ---------------------------------------------------------------------------
// kernel_launch
// Inputs (metadata order): x [N,128] f32, batch [N] (int32 on device), gate_w,
//                          gate_b, nn_w [128,256] f32, nn_b [256] f32
// Output: [16384, 256] f32
// ---------------------------------------------------------------------------
extern "C" void kernel_launch(void* const* d_in, const int* in_sizes, int n_in,
                              void* d_out, int out_size) {
    const float* x      = (const float*)d_in[0];
    const int*   batch  = (const int*)d_in[1];
    const float* gate_w = (const float*)d_in[2];
    const float* gate_b = (const float*)d_in[3];
    const float* nn_w   = (const float*)d_in[4];
    const float* nn_b   = (const float*)d_in[5];
    float*       out    = (float*)d_out;

    const int N = in_sizes[1];   // number of nodes

    seg_offsets_kernel<<<(NUM_GRAPHS + 1 + 255) / 256, 256>>>(batch, N);
    pool_kernel<<<NUM_GRAPHS / 8, 256>>>(
        reinterpret_cast<const float4*>(x),
        reinterpret_cast<const float4*>(gate_w),
        gate_b);
    gemm_kernel<<<NUM_GRAPHS / 16, 256>>>(nn_w, nn_b, out);
}

// round 3
// speedup vs baseline: 1.1991x; 1.1991x over previous
#include <cuda_runtime.h>

#define NUM_GRAPHS 16384
#define C 128
#define C2 256

// Scratch (static device globals — no allocation in kernel_launch)
__device__ int   g_offs[NUM_GRAPHS + 1];
__device__ float g_pooled[(size_t)NUM_GRAPHS * C];

// ---------------------------------------------------------------------------
// Kernel 0: segment offsets via coalesced boundary scan (batch is sorted).
// g_offs[g] = first index i with batch[i] >= g.
// Dtype-robust: JAX x64-disabled stores "int64" as int32; probe an odd 32-bit
// word (int64 high word == 0, int32 late id > 0).
// ---------------------------------------------------------------------------
__global__ void seg_offsets_kernel(const int* __restrict__ batch32, int n) {
    int i = blockIdx.x * blockDim.x + threadIdx.x;
    if (i >= n) return;

    int probe_idx = ((n - 1) & 1) ? (n - 1) : (n - 2);   // odd index < n
    bool is_i32 = (probe_idx >= 1) && (__ldg(&batch32[probe_idx]) != 0);

    int cur, nxt;
    if (is_i32) {
        cur = batch32[i];
        nxt = (i + 1 < n) ? batch32[i + 1] : NUM_GRAPHS;
    } else {
        cur = batch32[2 * i];                            // little-endian low word
        nxt = (i + 1 < n) ? batch32[2 * (i + 1)] : NUM_GRAPHS;
    }

    if (i == 0) {
        for (int g = 0; g <= cur; ++g) g_offs[g] = 0;
    }
    for (int g = cur + 1; g <= nxt; ++g) g_offs[g] = i + 1;
}

// ---------------------------------------------------------------------------
// Kernel 1: fused gate + online segment-softmax + weighted pooling.
// One warp per graph, lane = 4 channels (float4). Rows processed 4 at a time:
// 4 independent shuffle-reduce chains (ILP) + one rescale per group.
// ---------------------------------------------------------------------------
__global__ __launch_bounds__(256) void pool_kernel(
    const float4* __restrict__ x4,        // [N, 32] float4 view of [N,128]
    const float4* __restrict__ gate_w4,   // [32] float4 view of [128]
    const float*  __restrict__ gate_b)    // [1]
{
    const int warp = threadIdx.x >> 5;
    const int lane = threadIdx.x & 31;
    const int g = blockIdx.x * 8 + warp;

    const int lo = g_offs[g];
    const int hi = g_offs[g + 1];

    const float4 gw = gate_w4[lane];
    const float  gb = gate_b[0];

    float  m = -INFINITY;
    float  s = 0.0f;
    float4 acc = make_float4(0.f, 0.f, 0.f, 0.f);

    for (int r = lo; r < hi; r += 4) {
        // clamped row indices: padded rows get e=0 below, so value is harmless
        int r1 = min(r + 1, hi - 1);
        int r2 = min(r + 2, hi - 1);
        int r3 = min(r + 3, hi - 1);
        float4 v0 = x4[(size_t)r  * 32 + lane];
        float4 v1 = x4[(size_t)r1 * 32 + lane];
        float4 v2 = x4[(size_t)r2 * 32 + lane];
        float4 v3 = x4[(size_t)r3 * 32 + lane];

        float p0 = v0.x*gw.x + v0.y*gw.y + v0.z*gw.z + v0.w*gw.w;
        float p1 = v1.x*gw.x + v1.y*gw.y + v1.z*gw.z + v1.w*gw.w;
        float p2 = v2.x*gw.x + v2.y*gw.y + v2.z*gw.z + v2.w*gw.w;
        float p3 = v3.x*gw.x + v3.y*gw.y + v3.z*gw.z + v3.w*gw.w;

        #pragma unroll
        for (int o = 16; o > 0; o >>= 1) {
            p0 += __shfl_xor_sync(0xffffffffu, p0, o);
            p1 += __shfl_xor_sync(0xffffffffu, p1, o);
            p2 += __shfl_xor_sync(0xffffffffu, p2, o);
            p3 += __shfl_xor_sync(0xffffffffu, p3, o);
        }

        float s0 = p0 + gb;
        float s1 = (r + 1 < hi) ? (p1 + gb) : -INFINITY;
        float s2 = (r + 2 < hi) ? (p2 + gb) : -INFINITY;
        float s3 = (r + 3 < hi) ? (p3 + gb) : -INFINITY;

        float mg    = fmaxf(fmaxf(s0, s1), fmaxf(s2, s3));
        float m_new = fmaxf(m, mg);
        float alpha = __expf(m - m_new);          // exp(-inf)=0 on first group
        float e0 = __expf(s0 - m_new);
        float e1 = __expf(s1 - m_new);
        float e2 = __expf(s2 - m_new);
        float e3 = __expf(s3 - m_new);

        s = fmaf(s, alpha, (e0 + e1) + (e2 + e3));
        acc.x = fmaf(acc.x, alpha, fmaf(e3, v3.x, fmaf(e2, v2.x, fmaf(e1, v1.x, e0 * v0.x))));
        acc.y = fmaf(acc.y, alpha, fmaf(e3, v3.y, fmaf(e2, v2.y, fmaf(e1, v1.y, e0 * v0.y))));
        acc.z = fmaf(acc.z, alpha, fmaf(e3, v3.z, fmaf(e2, v2.z, fmaf(e1, v1.z, e0 * v0.z))));
        acc.w = fmaf(acc.w, alpha, fmaf(e3, v3.w, fmaf(e2, v2.w, fmaf(e1, v1.w, e0 * v0.w))));
        m = m_new;
    }

    float inv = (hi > lo) ? __frcp_rn(s) : 0.0f;
    float4 outv;
    outv.x = acc.x * inv;
    outv.y = acc.y * inv;
    outv.z = acc.z * inv;
    outv.w = acc.w * inv;
    reinterpret_cast<float4*>(g_pooled)[(size_t)g * 32 + lane] = outv;
}

// ---------------------------------------------------------------------------
// Kernel 2: out = pooled @ nn_w + nn_b (empty-graph zeroing), using packed
// fp32x2 FMA (sm_103a). Two k-partials per accumulator; ps pairs read as the
// 64-bit lanes of an LDS.128.
// ---------------------------------------------------------------------------
__device__ __forceinline__ void fma_f32x2(unsigned long long& d,
                                          unsigned long long a,
                                          unsigned long long b,
                                          unsigned long long c) {
    asm("fma.rn.f32x2 %0, %1, %2, %3;" : "=l"(d) : "l"(a), "l"(b), "l"(c));
}

__global__ __launch_bounds__(256) void gemm_kernel(
    const float* __restrict__ nn_w,   // [128, 256] row-major
    const float* __restrict__ nn_b,   // [256]
    float* __restrict__ out)          // [16384, 256]
{
    __shared__ float ps[16][C];       // pooled tile: 16 graphs x 128 ch = 8 KB

    const int t  = threadIdx.x;       // 0..255 -> output column j
    const int g0 = blockIdx.x * 16;

    // cooperative load of pooled tile (float4, coalesced)
    {
        const float4* src = reinterpret_cast<const float4*>(g_pooled + (size_t)g0 * C);
        float4* dst = reinterpret_cast<float4*>(&ps[0][0]);
        dst[t]       = src[t];
        dst[t + 256] = src[t + 256];
    }
    __syncthreads();

    const int j = t;
    unsigned long long acc2[16];
    #pragma unroll
    for (int g = 0; g < 16; ++g) acc2[g] = 0ull;

    #pragma unroll 1
    for (int k = 0; k < C; k += 4) {
        float w0 = nn_w[(k + 0) * C2 + j];
        float w1 = nn_w[(k + 1) * C2 + j];
        float w2 = nn_w[(k + 2) * C2 + j];
        float w3 = nn_w[(k + 3) * C2 + j];
        unsigned long long wp01, wp23;
        asm("mov.b64 %0, {%1, %2};" : "=l"(wp01) : "f"(w0), "f"(w1));
        asm("mov.b64 %0, {%1, %2};" : "=l"(wp23) : "f"(w2), "f"(w3));

        #pragma unroll
        for (int g = 0; g < 16; ++g) {
            ulonglong2 p = *reinterpret_cast<const ulonglong2*>(&ps[g][k]); // LDS.128
            fma_f32x2(acc2[g], p.x, wp01, acc2[g]);
            fma_f32x2(acc2[g], p.y, wp23, acc2[g]);
        }
    }

    const float b = nn_b[j];
    #pragma unroll
    for (int g = 0; g < 16; ++g) {
        float alo, ahi;
        asm("mov.b64 {%0, %1}, %2;" : "=f"(alo), "=f"(ahi) : "l"(acc2[g]));
        bool nonempty = g_offs[g0 + g + 1] > g_offs[g0 + g];
        out[(size_t)(g0 + g) * C2 + j] = nonempty ? (alo + ahi + b) : 0.0f;
    }
}

// ---------------------------------------------------------------------------
// kernel_launch
// Inputs (metadata order): x [N,128] f32, batch [N] (int32 on device), gate_w,
//                          gate_b, nn_w [128,256] f32, nn_b [256] f32
// Output: [16384, 256] f32
// ---------------------------------------------------------------------------
extern "C" void kernel_launch(void* const* d_in, const int* in_sizes, int n_in,
                              void* d_out, int out_size) {
    const float* x      = (const float*)d_in[0];
    const int*   batch  = (const int*)d_in[1];
    const float* gate_w = (const float*)d_in[2];
    const float* gate_b = (const float*)d_in[3];
    const float* nn_w   = (const float*)d_in[4];
    const float* nn_b   = (const float*)d_in[5];
    float*       out    = (float*)d_out;

    const int N = in_sizes[1];   // number of nodes

    seg_offsets_kernel<<<(N + 255) / 256, 256>>>(batch, N);
    pool_kernel<<<NUM_GRAPHS / 8, 256>>>(
        reinterpret_cast<const float4*>(x),
        reinterpret_cast<const float4*>(gate_w),
        gate_b);
    gemm_kernel<<<NUM_GRAPHS / 16, 256>>>(nn_w, nn_b, out);
}

// round 5
// speedup vs baseline: 1.2002x; 1.0009x over previous
#include <cuda_runtime.h>

#define NUM_GRAPHS 16384
#define C 128
#define C2 256

// Scratch (static device globals — no allocation in kernel_launch)
__device__ int   g_offs[NUM_GRAPHS + 1];
__device__ float g_pooled[(size_t)NUM_GRAPHS * C];

// ---------------------------------------------------------------------------
// Kernel 0: segment offsets via vectorized coalesced boundary scan.
// Each thread handles 4 logical elements. g_offs[g] = first i with batch[i]>=g.
// Dtype-robust: JAX x64-disabled stores "int64" as int32; probe an odd 32-bit
// word (int64 high word == 0, int32 late id > 0).
// ---------------------------------------------------------------------------
__global__ void seg_offsets_kernel(const int* __restrict__ batch32, int n) {
    int tid  = blockIdx.x * blockDim.x + threadIdx.x;
    int base = tid * 4;
    if (base >= n) return;

    int probe_idx = ((n - 1) & 1) ? (n - 1) : (n - 2);   // odd index < n
    bool is_i32 = (probe_idx >= 1) && (__ldg(&batch32[probe_idx]) != 0);

    int c[5];
    if (is_i32) {
        if (base + 4 <= n) {
            int4 q = *reinterpret_cast<const int4*>(batch32 + base);
            c[0] = q.x; c[1] = q.y; c[2] = q.z; c[3] = q.w;
        } else {
            #pragma unroll
            for (int k = 0; k < 4; ++k)
                c[k] = (base + k < n) ? batch32[base + k] : NUM_GRAPHS;
        }
        c[4] = (base + 4 < n) ? batch32[base + 4] : NUM_GRAPHS;
    } else {
        #pragma unroll
        for (int k = 0; k < 5; ++k)
            c[k] = (base + k < n) ? batch32[2 * (base + k)] : NUM_GRAPHS;
    }

    if (base == 0) {
        for (int g = 0; g <= c[0]; ++g) g_offs[g] = 0;
    }
    #pragma unroll
    for (int k = 0; k < 4; ++k) {
        int j = base + k;
        if (j >= n) break;
        for (int g = c[k] + 1; g <= c[k + 1]; ++g) g_offs[g] = j + 1;
    }
}

// ---------------------------------------------------------------------------
// Kernel 1: fused gate + online segment-softmax + weighted pooling.
// One warp per graph, lane = 4 channels (float4). 4 rows per group with
// explicit prefetch of the next group (8 LDG.128 in flight per warp).
// The 4 row-sums are reduced together: 2 merge levels (payload swap) put
// S_{lane%4} on each lane, 3 butterfly levels finish, 4 broadcasts fan out.
// 10 SHFL per group instead of 20.
// ---------------------------------------------------------------------------
__global__ __launch_bounds__(256) void pool_kernel(
    const float4* __restrict__ x4,        // [N, 32] float4 view of [N,128]
    const float4* __restrict__ gate_w4,   // [32] float4 view of [128]
    const float*  __restrict__ gate_b)    // [1]
{
    const int warp = threadIdx.x >> 5;
    const int lane = threadIdx.x & 31;
    const int g = blockIdx.x * 8 + warp;

    const int lo = g_offs[g];
    const int hi = g_offs[g + 1];

    float4* pooled_out = reinterpret_cast<float4*>(g_pooled) + (size_t)g * 32 + lane;

    if (lo >= hi) {
        *pooled_out = make_float4(0.f, 0.f, 0.f, 0.f);
        return;
    }

    const float4 gw = gate_w4[lane];
    const float  gb = gate_b[0];

    float  m = -INFINITY;
    float  s = 0.0f;
    float4 acc = make_float4(0.f, 0.f, 0.f, 0.f);

    const int last = hi - 1;

    // initial group load (clamped)
    float4 v0 = x4[(size_t)lo * 32 + lane];
    float4 v1 = x4[(size_t)min(lo + 1, last) * 32 + lane];
    float4 v2 = x4[(size_t)min(lo + 2, last) * 32 + lane];
    float4 v3 = x4[(size_t)min(lo + 3, last) * 32 + lane];

    for (int r = lo; r < hi; r += 4) {
        // prefetch next group (clamped; last-iter redundant loads are L1 hits)
        int rn = r + 4;
        float4 n0 = x4[(size_t)min(rn + 0, last) * 32 + lane];
        float4 n1 = x4[(size_t)min(rn + 1, last) * 32 + lane];
        float4 n2 = x4[(size_t)min(rn + 2, last) * 32 + lane];
        float4 n3 = x4[(size_t)min(rn + 3, last) * 32 + lane];

        // per-lane gate partials (4 independent rows)
        float p0 = v0.x*gw.x + v0.y*gw.y + v0.z*gw.z + v0.w*gw.w;
        float p1 = v1.x*gw.x + v1.y*gw.y + v1.z*gw.z + v1.w*gw.w;
        float p2 = v2.x*gw.x + v2.y*gw.y + v2.z*gw.z + v2.w*gw.w;
        float p3 = v3.x*gw.x + v3.y*gw.y + v3.z*gw.z + v3.w*gw.w;

        // merged 4-sum warp reduction (10 SHFL total)
        float ua = (lane & 1) ? p1 : p0;
        float ub = (lane & 1) ? p0 : p1;
        ua += __shfl_xor_sync(0xffffffffu, ub, 1);
        float va = (lane & 1) ? p3 : p2;
        float vb = (lane & 1) ? p2 : p3;
        va += __shfl_xor_sync(0xffffffffu, vb, 1);
        float wa = (lane & 2) ? va : ua;
        float wb = (lane & 2) ? ua : va;
        wa += __shfl_xor_sync(0xffffffffu, wb, 2);
        wa += __shfl_xor_sync(0xffffffffu, wa, 4);
        wa += __shfl_xor_sync(0xffffffffu, wa, 8);
        wa += __shfl_xor_sync(0xffffffffu, wa, 16);
        // lane j (j=0..3) now holds S_j; broadcast all four
        float s0 = __shfl_sync(0xffffffffu, wa, 0) + gb;
        float s1 = __shfl_sync(0xffffffffu, wa, 1) + gb;
        float s2 = __shfl_sync(0xffffffffu, wa, 2) + gb;
        float s3 = __shfl_sync(0xffffffffu, wa, 3) + gb;

        // mask padded rows
        if (r + 1 >= hi) s1 = -INFINITY;
        if (r + 2 >= hi) s2 = -INFINITY;
        if (r + 3 >= hi) s3 = -INFINITY;

        float mg    = fmaxf(fmaxf(s0, s1), fmaxf(s2, s3));
        float m_new = fmaxf(m, mg);
        float alpha = __expf(m - m_new);          // exp(-inf)=0 on first group
        float e0 = __expf(s0 - m_new);
        float e1 = __expf(s1 - m_new);
        float e2 = __expf(s2 - m_new);
        float e3 = __expf(s3 - m_new);

        s = fmaf(s, alpha, (e0 + e1) + (e2 + e3));
        acc.x = fmaf(acc.x, alpha, fmaf(e1, v1.x, e0 * v0.x) + fmaf(e3, v3.x, e2 * v2.x));
        acc.y = fmaf(acc.y, alpha, fmaf(e1, v1.y, e0 * v0.y) + fmaf(e3, v3.y, e2 * v2.y));
        acc.z = fmaf(acc.z, alpha, fmaf(e1, v1.z, e0 * v0.z) + fmaf(e3, v3.z, e2 * v2.z));
        acc.w = fmaf(acc.w, alpha, fmaf(e1, v1.w, e0 * v0.w) + fmaf(e3, v3.w, e2 * v2.w));
        m = m_new;

        v0 = n0; v1 = n1; v2 = n2; v3 = n3;
    }

    float inv = __frcp_rn(s);
    float4 outv;
    outv.x = acc.x * inv;
    outv.y = acc.y * inv;
    outv.z = acc.z * inv;
    outv.w = acc.w * inv;
    *pooled_out = outv;
}

// ---------------------------------------------------------------------------
// Kernel 2: out = pooled @ nn_w + nn_b (empty-graph zeroing), using packed
// fp32x2 FMA (sm_103a). Two k-partials per accumulator; ps pairs read as the
// 64-bit lanes of an LDS.128.
// ---------------------------------------------------------------------------
__device__ __forceinline__ void fma_f32x2(unsigned long long& d,
                                          unsigned long long a,
                                          unsigned long long b,
                                          unsigned long long c) {
    asm("fma.rn.f32x2 %0, %1, %2, %3;" : "=l"(d) : "l"(a), "l"(b), "l"(c));
}

__global__ __launch_bounds__(256) void gemm_kernel(
    const float* __restrict__ nn_w,   // [128, 256] row-major
    const float* __restrict__ nn_b,   // [256]
    float* __restrict__ out)          // [16384, 256]
{
    __shared__ float ps[16][C];       // pooled tile: 16 graphs x 128 ch = 8 KB

    const int t  = threadIdx.x;       // 0..255 -> output column j
    const int g0 = blockIdx.x * 16;

    // cooperative load of pooled tile (float4, coalesced)
    {
        const float4* src = reinterpret_cast<const float4*>(g_pooled + (size_t)g0 * C);
        float4* dst = reinterpret_cast<float4*>(&ps[0][0]);
        dst[t]       = src[t];
        dst[t + 256] = src[t + 256];
    }
    __syncthreads();

    const int j = t;
    unsigned long long acc2[16];
    #pragma unroll
    for (int g = 0; g < 16; ++g) acc2[g] = 0ull;

    #pragma unroll 1
    for (int k = 0; k < C; k += 4) {
        float w0 = nn_w[(k + 0) * C2 + j];
        float w1 = nn_w[(k + 1) * C2 + j];
        float w2 = nn_w[(k + 2) * C2 + j];
        float w3 = nn_w[(k + 3) * C2 + j];
        unsigned long long wp01, wp23;
        asm("mov.b64 %0, {%1, %2};" : "=l"(wp01) : "f"(w0), "f"(w1));
        asm("mov.b64 %0, {%1, %2};" : "=l"(wp23) : "f"(w2), "f"(w3));

        #pragma unroll
        for (int g = 0; g < 16; ++g) {
            ulonglong2 p = *reinterpret_cast<const ulonglong2*>(&ps[g][k]); // LDS.128
            fma_f32x2(acc2[g], p.x, wp01, acc2[g]);
            fma_f32x2(acc2[g], p.y, wp23, acc2[g]);
        }
    }

    const float b = nn_b[j];
    #pragma unroll
    for (int g = 0; g < 16; ++g) {
        float alo, ahi;
        asm("mov.b64 {%0, %1}, %2;" : "=f"(alo), "=f"(ahi) : "l"(acc2[g]));
        bool nonempty = g_offs[g0 + g + 1] > g_offs[g0 + g];
        out[(size_t)(g0 + g) * C2 + j] = nonempty ? (alo + ahi + b) : 0.0f;
    }
}

// ---------------------------------------------------------------------------
// kernel_launch
// Inputs (metadata order): x [N,128] f32, batch [N] (int32 on device), gate_w,
//                          gate_b, nn_w [128,256] f32, nn_b [256] f32
// Output: [16384, 256] f32
// ---------------------------------------------------------------------------
extern "C" void kernel_launch(void* const* d_in, const int* in_sizes, int n_in,
                              void* d_out, int out_size) {
    const float* x      = (const float*)d_in[0];
    const int*   batch  = (const int*)d_in[1];
    const float* gate_w = (const float*)d_in[2];
    const float* gate_b = (const float*)d_in[3];
    const float* nn_w   = (const float*)d_in[4];
    const float* nn_b   = (const float*)d_in[5];
    float*       out    = (float*)d_out;

    const int N = in_sizes[1];   // number of nodes

    int seg_threads = (N + 3) / 4;
    seg_offsets_kernel<<<(seg_threads + 255) / 256, 256>>>(batch, N);
    pool_kernel<<<NUM_GRAPHS / 8, 256>>>(
        reinterpret_cast<const float4*>(x),
        reinterpret_cast<const float4*>(gate_w),
        gate_b);
    gemm_kernel<<<NUM_GRAPHS / 16, 256>>>(nn_w, nn_b, out);
}